// round 1
// baseline (speedup 1.0000x reference)
#include <cuda_runtime.h>

// Fixed problem shape: B=8, S=4096, D=512, E=16
#define N_TOK 32768
#define DIM   512
#define NEXP  16
#define CAP   2457   // int(1.2 * 32768 / 16)

// ---------------- scratch (device globals; no allocation allowed) ----------
__device__ int   g_routes[N_TOK];
__device__ float g_probs[N_TOK];
__device__ int   g_pos[N_TOK];
__device__ int   g_idx[NEXP * CAP];
__device__ int   g_count[NEXP];

// ---------------- 1) router: logits, argmax, softmax-max prob --------------
// one warp per token; switch_w cached in shared (16x512 f32 = 32KB)
__global__ void router_kernel(const float* __restrict__ x,
                              const float* __restrict__ sw,
                              const float* __restrict__ sb) {
    __shared__ float s_w[NEXP][DIM];
    __shared__ float s_b[NEXP];
    int tid = threadIdx.x;
    for (int i = tid; i < NEXP * DIM; i += 256)
        (&s_w[0][0])[i] = sw[i];
    if (tid < NEXP) s_b[tid] = sb[tid];
    __syncthreads();

    int warp = tid >> 5, lane = tid & 31;
    int t = blockIdx.x * 8 + warp;
    const float* xr = x + (size_t)t * DIM;

    float acc[NEXP];
#pragma unroll
    for (int e = 0; e < NEXP; e++) acc[e] = 0.f;

#pragma unroll
    for (int j = 0; j < DIM / 32; j++) {
        float xv = xr[lane + 32 * j];
#pragma unroll
        for (int e = 0; e < NEXP; e++)
            acc[e] += xv * s_w[e][lane + 32 * j];
    }
#pragma unroll
    for (int e = 0; e < NEXP; e++) {
#pragma unroll
        for (int off = 16; off > 0; off >>= 1)
            acc[e] += __shfl_xor_sync(0xffffffffu, acc[e], off);
    }
    if (lane == 0) {
        float lmax = -1e30f; int am = 0;
#pragma unroll
        for (int e = 0; e < NEXP; e++) {
            float l = acc[e] + s_b[e];
            acc[e] = l;
            if (l > lmax) { lmax = l; am = e; }
        }
        float sum = 0.f;
#pragma unroll
        for (int e = 0; e < NEXP; e++) sum += expf(acc[e] - lmax);
        g_routes[t] = am;
        g_probs[t]  = 1.f / sum;   // softmax value at the max logit
    }
}

// ---------------- 2) ordered rank within each expert queue -----------------
// one block per expert; block-wide scan over token order (preserves order)
__global__ void rank_kernel() {
    int e = blockIdx.x;
    int tid = threadIdx.x;
    int lane = tid & 31, wid = tid >> 5;
    __shared__ int s_ws[32];
    __shared__ int s_total;
    int base = 0;
    for (int c = 0; c < N_TOK; c += 1024) {
        int i = c + tid;
        int flag = (g_routes[i] == e) ? 1 : 0;
        unsigned mask = __ballot_sync(0xffffffffu, flag);
        int wr = __popc(mask & ((1u << lane) - 1u));
        if (lane == 0) s_ws[wid] = __popc(mask);
        __syncthreads();
        if (wid == 0) {
            int v = s_ws[lane];
            int inc = v;
#pragma unroll
            for (int off = 1; off < 32; off <<= 1) {
                int o = __shfl_up_sync(0xffffffffu, inc, off);
                if (lane >= off) inc += o;
            }
            s_ws[lane] = inc - v;              // exclusive prefix of warp sums
            if (lane == 31) s_total = inc;     // total this chunk
        }
        __syncthreads();
        if (flag) {
            int p = base + s_ws[wid] + wr;
            g_pos[i] = p;
            if (p < CAP) g_idx[e * CAP + p] = i;
        }
        base += s_total;
        __syncthreads();
    }
    if (tid == 0) g_count[e] = base < CAP ? base : CAP;
}

// ---------------- 3) passthrough for dropped tokens ------------------------
__global__ void passthrough_kernel(const float* __restrict__ x,
                                   float* __restrict__ out) {
    int t = blockIdx.x;
    if (g_pos[t] >= CAP) {
        float p = g_probs[t];
        const float4* xr = (const float4*)(x + (size_t)t * DIM);
        float4* o = (float4*)(out + (size_t)t * DIM);
        for (int i = threadIdx.x; i < DIM / 4; i += blockDim.x) {
            float4 v = xr[i];
            v.x *= p; v.y *= p; v.z *= p; v.w *= p;
            o[i] = v;
        }
    }
}

// ---------------- 4) grouped gather-GEMM with fused combine ----------------
// y[tok] = (x[tok] @ W_e^T + b_e) * prob[tok], scattered directly to out.
// 128x128x8 tile, 256 threads, 8x8 per thread (split 4+4 to avoid bank
// conflicts), double-buffered shared.
#define BM 128
#define BN 128
#define BK 8

__global__ void __launch_bounds__(256)
moe_gemm_kernel(const float* __restrict__ x,
                const float* __restrict__ ew,
                const float* __restrict__ eb,
                float* __restrict__ out) {
    int e = blockIdx.z;
    int cnt = g_count[e];
    int m0 = blockIdx.x * BM;
    if (m0 >= cnt) return;
    int n0 = blockIdx.y * BN;

    __shared__ float As[2][BK][BM];
    __shared__ float Bs[2][BK][BN];
    __shared__ int s_idx[BM];

    int tid = threadIdx.x;
    if (tid < BM) {
        int m = m0 + tid;
        s_idx[tid] = g_idx[e * CAP + (m < cnt ? m : cnt - 1)];
    }
    __syncthreads();

    const float* W = ew + (size_t)e * DIM * DIM;

    int a_row = tid >> 1;            // 0..127
    int a_col = (tid & 1) * 4;       // 0 or 4
    int a_tok = s_idx[a_row];
    const float* a_src = x + (size_t)a_tok * DIM + a_col;
    const float* b_src = W + (size_t)(n0 + a_row) * DIM + a_col;

    // prefetch k-tile 0
    {
        float4 av = *(const float4*)(a_src);
        float4 bv = *(const float4*)(b_src);
        As[0][a_col + 0][a_row] = av.x; As[0][a_col + 1][a_row] = av.y;
        As[0][a_col + 2][a_row] = av.z; As[0][a_col + 3][a_row] = av.w;
        Bs[0][a_col + 0][a_row] = bv.x; Bs[0][a_col + 1][a_row] = bv.y;
        Bs[0][a_col + 2][a_row] = bv.z; Bs[0][a_col + 3][a_row] = bv.w;
    }
    __syncthreads();

    float c[8][8];
#pragma unroll
    for (int i = 0; i < 8; i++)
#pragma unroll
        for (int j = 0; j < 8; j++) c[i][j] = 0.f;

    int ty = tid >> 4, tx = tid & 15;
    const int row_off0 = ty * 4, row_off1 = 64 + ty * 4;
    const int col_off0 = tx * 4, col_off1 = 64 + tx * 4;

    const int KT = DIM / BK;   // 64
#pragma unroll 1
    for (int kt = 0; kt < KT; kt++) {
        int cur = kt & 1;
        float4 na, nb;
        if (kt + 1 < KT) {
            int k = (kt + 1) * BK;
            na = *(const float4*)(a_src + k);
            nb = *(const float4*)(b_src + k);
        }
#pragma unroll
        for (int k = 0; k < BK; k++) {
            float4 a0 = *(const float4*)&As[cur][k][row_off0];
            float4 a1 = *(const float4*)&As[cur][k][row_off1];
            float4 b0 = *(const float4*)&Bs[cur][k][col_off0];
            float4 b1 = *(const float4*)&Bs[cur][k][col_off1];
            float av[8] = {a0.x, a0.y, a0.z, a0.w, a1.x, a1.y, a1.z, a1.w};
            float bv[8] = {b0.x, b0.y, b0.z, b0.w, b1.x, b1.y, b1.z, b1.w};
#pragma unroll
            for (int i = 0; i < 8; i++)
#pragma unroll
                for (int j = 0; j < 8; j++)
                    c[i][j] += av[i] * bv[j];
        }
        if (kt + 1 < KT) {
            int nxt = cur ^ 1;
            As[nxt][a_col + 0][a_row] = na.x; As[nxt][a_col + 1][a_row] = na.y;
            As[nxt][a_col + 2][a_row] = na.z; As[nxt][a_col + 3][a_row] = na.w;
            Bs[nxt][a_col + 0][a_row] = nb.x; Bs[nxt][a_col + 1][a_row] = nb.y;
            Bs[nxt][a_col + 2][a_row] = nb.z; Bs[nxt][a_col + 3][a_row] = nb.w;
            __syncthreads();
        }
    }

    // epilogue: +bias, *prob, scatter to out rows
    float bias[8];
#pragma unroll
    for (int j = 0; j < 4; j++) {
        bias[j]     = eb[e * DIM + n0 + col_off0 + j];
        bias[4 + j] = eb[e * DIM + n0 + col_off1 + j];
    }
#pragma unroll
    for (int ih = 0; ih < 2; ih++) {
        int rbase = (ih == 0) ? row_off0 : row_off1;
#pragma unroll
        for (int ii = 0; ii < 4; ii++) {
            int mloc = rbase + ii;
            int m = m0 + mloc;
            if (m < cnt) {
                int i = ih * 4 + ii;
                int tok = s_idx[mloc];
                float p = g_probs[tok];
                float* orow = out + (size_t)tok * DIM + n0;
                float4 v0 = make_float4((c[i][0] + bias[0]) * p,
                                        (c[i][1] + bias[1]) * p,
                                        (c[i][2] + bias[2]) * p,
                                        (c[i][3] + bias[3]) * p);
                float4 v1 = make_float4((c[i][4] + bias[4]) * p,
                                        (c[i][5] + bias[5]) * p,
                                        (c[i][6] + bias[6]) * p,
                                        (c[i][7] + bias[7]) * p);
                *(float4*)(orow + col_off0) = v0;
                *(float4*)(orow + col_off1) = v1;
            }
        }
    }
}

// ---------------------------------------------------------------------------
extern "C" void kernel_launch(void* const* d_in, const int* in_sizes, int n_in,
                              void* d_out, int out_size) {
    const float* x  = (const float*)d_in[0];   // [N, D] (flattened [B,S,D])
    const float* sw = (const float*)d_in[1];   // [E, D]
    const float* sb = (const float*)d_in[2];   // [E]
    const float* ew = (const float*)d_in[3];   // [E, D, D]
    const float* ebv = (const float*)d_in[4];  // [E, D]
    float* out = (float*)d_out;

    router_kernel<<<N_TOK / 8, 256>>>(x, sw, sb);
    rank_kernel<<<NEXP, 1024>>>();
    passthrough_kernel<<<N_TOK, 128>>>(x, out);
    dim3 grid((CAP + BM - 1) / BM, DIM / BN, NEXP);
    moe_gemm_kernel<<<grid, 256>>>(x, ew, ebv, out);
}

// round 3
// speedup vs baseline: 1.7187x; 1.7187x over previous
#include <cuda_runtime.h>
#include <cuda_bf16.h>
#include <cstdint>

// Fixed problem shape: B=8, S=4096, D=512, E=16
#define N_TOK 32768
#define DIM   512
#define NEXP  16
#define CAP   2457   // int(1.2 * 32768 / 16)

// ---------------- scratch (device globals; no allocation allowed) ----------
__device__ __align__(16) __nv_bfloat16 g_xh[N_TOK * DIM];
__device__ __align__(16) __nv_bfloat16 g_xl[N_TOK * DIM];
__device__ __align__(16) __nv_bfloat16 g_wh[NEXP * DIM * DIM];
__device__ __align__(16) __nv_bfloat16 g_wl[NEXP * DIM * DIM];
__device__ int   g_routes[N_TOK];
__device__ float g_probs[N_TOK];
__device__ int   g_pos[N_TOK];
__device__ int   g_idx[NEXP * CAP];
__device__ int   g_count[NEXP];

// ---------------- PTX helpers (baseline sm_80/sm_90 features only) ---------
__device__ __forceinline__ uint32_t smem_u32(const void* p) {
    uint32_t a;
    asm("{ .reg .u64 t; cvta.to.shared.u64 t, %1; cvt.u32.u64 %0, t; }"
        : "=r"(a) : "l"(p));
    return a;
}
__device__ __forceinline__ uint32_t swz(uint32_t b) {   // SW64-style swizzle
    return b ^ ((b >> 3) & 0x30);
}
__device__ __forceinline__ void cp16(uint32_t dst, const void* src) {
    asm volatile("cp.async.cg.shared.global [%0], [%1], 16;\n"
                 :: "r"(dst), "l"(src));
}
#define CP_COMMIT() asm volatile("cp.async.commit_group;\n" ::: "memory")
#define CP_WAIT1()  asm volatile("cp.async.wait_group 1;\n" ::: "memory")

__device__ __forceinline__ void ldsm4(uint32_t* r, uint32_t a) {
    asm volatile("ldmatrix.sync.aligned.m8n8.x4.shared.b16 {%0,%1,%2,%3}, [%4];\n"
                 : "=r"(r[0]), "=r"(r[1]), "=r"(r[2]), "=r"(r[3]) : "r"(a));
}
__device__ __forceinline__ void mma16816(float* d, const uint32_t* a,
                                         const uint32_t* b) {
    asm volatile(
        "mma.sync.aligned.m16n8k16.row.col.f32.bf16.bf16.f32 "
        "{%0,%1,%2,%3}, {%4,%5,%6,%7}, {%8,%9}, {%0,%1,%2,%3};\n"
        : "+f"(d[0]), "+f"(d[1]), "+f"(d[2]), "+f"(d[3])
        : "r"(a[0]), "r"(a[1]), "r"(a[2]), "r"(a[3]), "r"(b[0]), "r"(b[1]));
}

// ---------------- 1) router + x split-bf16 conversion -----------------------
// 4 tokens per warp: each W smem read feeds 4 FMAs (4x less LDS traffic).
__global__ void router_kernel(const float* __restrict__ x,
                              const float* __restrict__ sw,
                              const float* __restrict__ sb) {
    __shared__ float s_w[NEXP][DIM];
    __shared__ float s_b[NEXP];
    int tid = threadIdx.x;
    for (int i = tid; i < NEXP * DIM / 4; i += 256)
        ((float4*)&s_w[0][0])[i] = ((const float4*)sw)[i];
    if (tid < NEXP) s_b[tid] = sb[tid];
    __syncthreads();

    int warp = tid >> 5, lane = tid & 31;
    int t0 = blockIdx.x * 32 + warp * 4;

    float acc[4][NEXP];
#pragma unroll
    for (int tt = 0; tt < 4; tt++)
#pragma unroll
        for (int e = 0; e < NEXP; e++) acc[tt][e] = 0.f;

#pragma unroll
    for (int j = 0; j < DIM / 32; j++) {
        int k = lane + 32 * j;
        float xv[4];
#pragma unroll
        for (int tt = 0; tt < 4; tt++) {
            xv[tt] = x[(size_t)(t0 + tt) * DIM + k];
            __nv_bfloat16 h = __float2bfloat16_rn(xv[tt]);
            float hf = __bfloat162float(h);
            g_xh[(size_t)(t0 + tt) * DIM + k] = h;
            g_xl[(size_t)(t0 + tt) * DIM + k] = __float2bfloat16_rn(xv[tt] - hf);
        }
#pragma unroll
        for (int e = 0; e < NEXP; e++) {
            float w = s_w[e][k];
#pragma unroll
            for (int tt = 0; tt < 4; tt++)
                acc[tt][e] = fmaf(xv[tt], w, acc[tt][e]);
        }
    }
#pragma unroll
    for (int tt = 0; tt < 4; tt++)
#pragma unroll
        for (int e = 0; e < NEXP; e++)
#pragma unroll
            for (int off = 16; off > 0; off >>= 1)
                acc[tt][e] += __shfl_xor_sync(0xffffffffu, acc[tt][e], off);

#pragma unroll
    for (int tt = 0; tt < 4; tt++) {
        if (lane == tt) {
            float lmax = -1e30f; int am = 0;
#pragma unroll
            for (int e = 0; e < NEXP; e++) {
                float l = acc[tt][e] + s_b[e];
                acc[tt][e] = l;
                if (l > lmax) { lmax = l; am = e; }
            }
            float sum = 0.f;
#pragma unroll
            for (int e = 0; e < NEXP; e++) sum += expf(acc[tt][e] - lmax);
            g_routes[t0 + tt] = am;
            g_probs[t0 + tt]  = 1.f / sum;
        }
    }
}

// ---------------- 2) expert-weight split-bf16 conversion --------------------
__global__ void wconv_kernel(const float* __restrict__ ew) {
    int idx = blockIdx.x * 256 + threadIdx.x;           // float4 index
    float4 v = ((const float4*)ew)[idx];
    float hx = __bfloat162float(__float2bfloat16_rn(v.x));
    float hy = __bfloat162float(__float2bfloat16_rn(v.y));
    float hz = __bfloat162float(__float2bfloat16_rn(v.z));
    float hw = __bfloat162float(__float2bfloat16_rn(v.w));
    __nv_bfloat162 h0 = __floats2bfloat162_rn(hx, hy);
    __nv_bfloat162 h1 = __floats2bfloat162_rn(hz, hw);
    __nv_bfloat162 l0 = __floats2bfloat162_rn(v.x - hx, v.y - hy);
    __nv_bfloat162 l1 = __floats2bfloat162_rn(v.z - hz, v.w - hw);
    *(uint2*)(g_wh + (size_t)idx * 4) = make_uint2(*(uint32_t*)&h0, *(uint32_t*)&h1);
    *(uint2*)(g_wl + (size_t)idx * 4) = make_uint2(*(uint32_t*)&l0, *(uint32_t*)&l1);
}

// ---------------- 3) ordered rank within each expert queue ------------------
__global__ void rank_kernel() {
    int e = blockIdx.x;
    int tid = threadIdx.x, lane = tid & 31, wid = tid >> 5;
    __shared__ int s_ws[32];
    __shared__ int s_tot;
    int base = 0;
    const int4* r4 = (const int4*)g_routes;
#pragma unroll 1
    for (int c = 0; c < N_TOK / 4096; c++) {
        int4 r = r4[c * 1024 + tid];
        int f0 = (r.x == e), f1 = (r.y == e), f2 = (r.z == e), f3 = (r.w == e);
        int cnt = f0 + f1 + f2 + f3;
        int inc = cnt;
#pragma unroll
        for (int off = 1; off < 32; off <<= 1) {
            int o = __shfl_up_sync(0xffffffffu, inc, off);
            if (lane >= off) inc += o;
        }
        if (lane == 31) s_ws[wid] = inc;
        __syncthreads();
        if (wid == 0) {
            int v = s_ws[lane];
            int wi = v;
#pragma unroll
            for (int off = 1; off < 32; off <<= 1) {
                int o = __shfl_up_sync(0xffffffffu, wi, off);
                if (lane >= off) wi += o;
            }
            s_ws[lane] = wi - v;
            if (lane == 31) s_tot = wi;
        }
        __syncthreads();
        int ex = base + s_ws[wid] + (inc - cnt);
        int t = (c * 1024 + tid) * 4;
        if (f0) { g_pos[t]     = ex; if (ex < CAP) g_idx[e * CAP + ex] = t;     ex++; }
        if (f1) { g_pos[t + 1] = ex; if (ex < CAP) g_idx[e * CAP + ex] = t + 1; ex++; }
        if (f2) { g_pos[t + 2] = ex; if (ex < CAP) g_idx[e * CAP + ex] = t + 2; ex++; }
        if (f3) { g_pos[t + 3] = ex; if (ex < CAP) g_idx[e * CAP + ex] = t + 3; ex++; }
        base += s_tot;
        __syncthreads();
    }
    if (tid == 0) g_count[e] = base < CAP ? base : CAP;
}

// ---------------- 4) passthrough for dropped tokens (warp per token) --------
__global__ void passthrough_kernel(const float* __restrict__ x,
                                   float* __restrict__ out) {
    int warp = threadIdx.x >> 5, lane = threadIdx.x & 31;
    int t = blockIdx.x * 8 + warp;
    if (g_pos[t] >= CAP) {
        float p = g_probs[t];
        const float4* xr = (const float4*)(x + (size_t)t * DIM);
        float4* o = (float4*)(out + (size_t)t * DIM);
#pragma unroll
        for (int j = 0; j < 4; j++) {
            float4 v = xr[lane + 32 * j];
            v.x *= p; v.y *= p; v.z *= p; v.w *= p;
            o[lane + 32 * j] = v;
        }
    }
}

// ---------------- 5) mma.sync grouped gather-GEMM, fused combine ------------
// CTA tile 128x128x32, 8 warps (2x4), warp tile 64x32.
// Split-bf16: D += Ah*Bh + Ah*Bl + Al*Bh, fp32 accum in registers.
#define BM 128
#define BN 128
#define BK 32
#define NSTG 3
#define TERM_BYTES (BM * BK * 2)        // 8192
#define STG_BYTES  (4 * TERM_BYTES)     // 32768: Ah | Al | Bh | Bl
#define SMEM_DYN   (NSTG * STG_BYTES + 1024)

__global__ void __launch_bounds__(256, 1)
moe_mma_kernel(const float* __restrict__ eb, float* __restrict__ out) {
    extern __shared__ char dynsmem[];
    __shared__ int   s_idx[BM];
    __shared__ float s_prob[BM];
    __shared__ float s_bias[BN];

    int e = blockIdx.z;
    int cnt = g_count[e];
    int m0 = blockIdx.x * BM;
    if (m0 >= cnt) return;
    int n0 = blockIdx.y * BN;
    int tid = threadIdx.x, wid = tid >> 5, lane = tid & 31;
    int wm = wid >> 2, wn = wid & 3;

    char* sbase = dynsmem + ((1024u - (smem_u32(dynsmem) & 1023u)) & 1023u);
    uint32_t u0 = smem_u32(sbase);

    if (tid < BM) {
        int m = m0 + tid;
        int t = g_idx[e * CAP + (m < cnt ? m : cnt - 1)];
        s_idx[tid] = t;
        s_prob[tid] = g_probs[t];
    }
    if (tid < BN) s_bias[tid] = eb[e * DIM + n0 + tid];
    __syncthreads();

    // per-thread cp.async slots: 2 x (row, 16B chunk)
    const __nv_bfloat16 *srcAh[2], *srcAl[2], *srcBh[2], *srcBl[2];
    uint32_t sdst[2];
#pragma unroll
    for (int i = 0; i < 2; i++) {
        int idx = tid + 256 * i;
        int row = idx >> 2, ch = idx & 3;
        size_t ao = (size_t)s_idx[row] * DIM + ch * 8;
        srcAh[i] = g_xh + ao;
        srcAl[i] = g_xl + ao;
        size_t bo = (size_t)(e * DIM + n0 + row) * DIM + ch * 8;
        srcBh[i] = g_wh + bo;
        srcBl[i] = g_wl + bo;
        sdst[i] = swz((uint32_t)(row * 64 + ch * 16));
    }

    const int KT = DIM / BK;   // 16
    // prologue: stages 0,1
#pragma unroll
    for (int pre = 0; pre < 2; pre++) {
        uint32_t sb = u0 + pre * STG_BYTES;
        int kb = pre * BK;
#pragma unroll
        for (int i = 0; i < 2; i++) {
            cp16(sb + 0 * TERM_BYTES + sdst[i], srcAh[i] + kb);
            cp16(sb + 1 * TERM_BYTES + sdst[i], srcAl[i] + kb);
            cp16(sb + 2 * TERM_BYTES + sdst[i], srcBh[i] + kb);
            cp16(sb + 3 * TERM_BYTES + sdst[i], srcBl[i] + kb);
        }
        CP_COMMIT();
    }

    float acc[4][4][4];
#pragma unroll
    for (int mi = 0; mi < 4; mi++)
#pragma unroll
        for (int nj = 0; nj < 4; nj++)
#pragma unroll
            for (int k = 0; k < 4; k++) acc[mi][nj][k] = 0.f;

#pragma unroll 1
    for (int kt = 0; kt < KT; kt++) {
        CP_WAIT1();
        __syncthreads();
        if (kt + 2 < KT) {
            uint32_t sb = u0 + ((kt + 2) % NSTG) * STG_BYTES;
            int kb = (kt + 2) * BK;
#pragma unroll
            for (int i = 0; i < 2; i++) {
                cp16(sb + 0 * TERM_BYTES + sdst[i], srcAh[i] + kb);
                cp16(sb + 1 * TERM_BYTES + sdst[i], srcAl[i] + kb);
                cp16(sb + 2 * TERM_BYTES + sdst[i], srcBh[i] + kb);
                cp16(sb + 3 * TERM_BYTES + sdst[i], srcBl[i] + kb);
            }
            CP_COMMIT();
        } else {
            CP_COMMIT();   // keep group count in step
        }

        uint32_t sb = u0 + (kt % NSTG) * STG_BYTES;
#pragma unroll
        for (int ks = 0; ks < 2; ks++) {
            uint32_t ah[4][4], al[4][4], bh[4][2], bl[4][2];
#pragma unroll
            for (int mi = 0; mi < 4; mi++) {
                uint32_t off = (uint32_t)((wm * 64 + mi * 16 + (lane & 15)) * 64 +
                                          ks * 32 + (lane >> 4) * 16);
                uint32_t ad = sb + swz(off);
                ldsm4(ah[mi], ad);
                ldsm4(al[mi], ad + TERM_BYTES);
            }
#pragma unroll
            for (int nj2 = 0; nj2 < 2; nj2++) {
                uint32_t off = (uint32_t)((wn * 32 + nj2 * 16 +
                                           ((lane >> 4) & 1) * 8 + (lane & 7)) * 64 +
                                          ks * 32 + ((lane >> 3) & 1) * 16);
                uint32_t bd = sb + 2 * TERM_BYTES + swz(off);
                uint32_t r[4];
                ldsm4(r, bd);
                bh[nj2 * 2][0] = r[0]; bh[nj2 * 2][1] = r[1];
                bh[nj2 * 2 + 1][0] = r[2]; bh[nj2 * 2 + 1][1] = r[3];
                ldsm4(r, bd + TERM_BYTES);
                bl[nj2 * 2][0] = r[0]; bl[nj2 * 2][1] = r[1];
                bl[nj2 * 2 + 1][0] = r[2]; bl[nj2 * 2 + 1][1] = r[3];
            }
#pragma unroll
            for (int mi = 0; mi < 4; mi++)
#pragma unroll
                for (int nj = 0; nj < 4; nj++) {
                    mma16816(acc[mi][nj], ah[mi], bh[nj]);
                    mma16816(acc[mi][nj], ah[mi], bl[nj]);
                    mma16816(acc[mi][nj], al[mi], bh[nj]);
                }
        }
    }

    // epilogue: +bias, *prob, scatter rows to out
#pragma unroll
    for (int mi = 0; mi < 4; mi++) {
        int r0 = wm * 64 + mi * 16 + (lane >> 2);
        int r1 = r0 + 8;
        bool ok0 = (m0 + r0) < cnt;
        bool ok1 = (m0 + r1) < cnt;
        float p0 = s_prob[r0], p1 = s_prob[r1];
        float* o0 = out + (size_t)s_idx[r0] * DIM + n0;
        float* o1 = out + (size_t)s_idx[r1] * DIM + n0;
#pragma unroll
        for (int nj = 0; nj < 4; nj++) {
            int col = wn * 32 + nj * 8 + 2 * (lane & 3);
            float b0 = s_bias[col], b1 = s_bias[col + 1];
            if (ok0) {
                float2 v = make_float2((acc[mi][nj][0] + b0) * p0,
                                       (acc[mi][nj][1] + b1) * p0);
                *(float2*)(o0 + col) = v;
            }
            if (ok1) {
                float2 v = make_float2((acc[mi][nj][2] + b0) * p1,
                                       (acc[mi][nj][3] + b1) * p1);
                *(float2*)(o1 + col) = v;
            }
        }
    }
}

// ---------------------------------------------------------------------------
extern "C" void kernel_launch(void* const* d_in, const int* in_sizes, int n_in,
                              void* d_out, int out_size) {
    const float* x   = (const float*)d_in[0];   // [N, D]
    const float* sw  = (const float*)d_in[1];   // [E, D]
    const float* sb  = (const float*)d_in[2];   // [E]
    const float* ew  = (const float*)d_in[3];   // [E, D, D]
    const float* ebv = (const float*)d_in[4];   // [E, D]
    float* out = (float*)d_out;

    cudaFuncSetAttribute(moe_mma_kernel,
                         cudaFuncAttributeMaxDynamicSharedMemorySize, SMEM_DYN);

    router_kernel<<<N_TOK / 32, 256>>>(x, sw, sb);
    wconv_kernel<<<NEXP * DIM * DIM / 4 / 256, 256>>>(ew);
    rank_kernel<<<NEXP, 1024>>>();
    passthrough_kernel<<<N_TOK / 8, 256>>>(x, out);

    dim3 grid((CAP + BM - 1) / BM, DIM / BN, NEXP);
    moe_mma_kernel<<<grid, 256, SMEM_DYN>>>(ebv, out);
}

// round 4
// speedup vs baseline: 1.8615x; 1.0831x over previous
#include <cuda_runtime.h>
#include <cuda_bf16.h>
#include <cstdint>

// Fixed problem shape: B=8, S=4096, D=512, E=16
#define N_TOK 32768
#define DIM   512
#define NEXP  16
#define CAP   2457   // int(1.2 * 32768 / 16)

// ---------------- scratch (device globals; no allocation allowed) ----------
__device__ __align__(16) __nv_bfloat16 g_xh[N_TOK * DIM];
__device__ __align__(16) __nv_bfloat16 g_xl[N_TOK * DIM];
__device__ __align__(16) __nv_bfloat16 g_wh[NEXP * DIM * DIM];
__device__ __align__(16) __nv_bfloat16 g_wl[NEXP * DIM * DIM];
__device__ int   g_routes[N_TOK];
__device__ float g_probs[N_TOK];
__device__ int   g_pos[N_TOK];
__device__ int   g_idx[NEXP * CAP];
__device__ int   g_count[NEXP];

// ---------------- PTX helpers (baseline sm_80/sm_90 features only) ---------
__device__ __forceinline__ uint32_t smem_u32(const void* p) {
    uint32_t a;
    asm("{ .reg .u64 t; cvta.to.shared.u64 t, %1; cvt.u32.u64 %0, t; }"
        : "=r"(a) : "l"(p));
    return a;
}
__device__ __forceinline__ uint32_t swz(uint32_t b) {   // 64B-row swizzle
    return b ^ ((b >> 3) & 0x30);
}
__device__ __forceinline__ void cp16(uint32_t dst, const void* src) {
    asm volatile("cp.async.cg.shared.global [%0], [%1], 16;\n"
                 :: "r"(dst), "l"(src));
}
#define CP_COMMIT() asm volatile("cp.async.commit_group;\n" ::: "memory")
#define CP_WAIT1()  asm volatile("cp.async.wait_group 1;\n" ::: "memory")

__device__ __forceinline__ void ldsm4(uint32_t* r, uint32_t a) {
    asm volatile("ldmatrix.sync.aligned.m8n8.x4.shared.b16 {%0,%1,%2,%3}, [%4];\n"
                 : "=r"(r[0]), "=r"(r[1]), "=r"(r[2]), "=r"(r[3]) : "r"(a));
}
__device__ __forceinline__ void mma16816(float* d, const uint32_t* a,
                                         const uint32_t* b) {
    asm volatile(
        "mma.sync.aligned.m16n8k16.row.col.f32.bf16.bf16.f32 "
        "{%0,%1,%2,%3}, {%4,%5,%6,%7}, {%8,%9}, {%0,%1,%2,%3};\n"
        : "+f"(d[0]), "+f"(d[1]), "+f"(d[2]), "+f"(d[3])
        : "r"(a[0]), "r"(a[1]), "r"(a[2]), "r"(a[3]), "r"(b[0]), "r"(b[1]));
}

// ---------------- 1) fused router + x-split + W-split -----------------------
// blocks [0, 1024): router (32 tokens/block, 4/warp) + x hi/lo split
// blocks [1024, 5120): expert-weight hi/lo split (elementwise)
#define RW_ROUTER_BLOCKS (N_TOK / 32)                       // 1024
#define RW_WCONV_BLOCKS  (NEXP * DIM * DIM / 4 / 256)       // 4096

__global__ void __launch_bounds__(256)
rw_kernel(const float* __restrict__ x,
          const float* __restrict__ sw,
          const float* __restrict__ sb,
          const float* __restrict__ ew) {
    int tid = threadIdx.x;

    if (blockIdx.x >= RW_ROUTER_BLOCKS) {
        // ---- wconv part ----
        int idx = (blockIdx.x - RW_ROUTER_BLOCKS) * 256 + tid;   // float4 index
        float4 v = ((const float4*)ew)[idx];
        float hx = __bfloat162float(__float2bfloat16_rn(v.x));
        float hy = __bfloat162float(__float2bfloat16_rn(v.y));
        float hz = __bfloat162float(__float2bfloat16_rn(v.z));
        float hw = __bfloat162float(__float2bfloat16_rn(v.w));
        __nv_bfloat162 h0 = __floats2bfloat162_rn(hx, hy);
        __nv_bfloat162 h1 = __floats2bfloat162_rn(hz, hw);
        __nv_bfloat162 l0 = __floats2bfloat162_rn(v.x - hx, v.y - hy);
        __nv_bfloat162 l1 = __floats2bfloat162_rn(v.z - hz, v.w - hw);
        *(uint2*)(g_wh + (size_t)idx * 4) = make_uint2(*(uint32_t*)&h0, *(uint32_t*)&h1);
        *(uint2*)(g_wl + (size_t)idx * 4) = make_uint2(*(uint32_t*)&l0, *(uint32_t*)&l1);
        return;
    }

    // ---- router part ----
    __shared__ float s_w[NEXP][DIM];
    __shared__ float s_b[NEXP];
    for (int i = tid; i < NEXP * DIM / 4; i += 256)
        ((float4*)&s_w[0][0])[i] = ((const float4*)sw)[i];
    if (tid < NEXP) s_b[tid] = sb[tid];
    __syncthreads();

    int warp = tid >> 5, lane = tid & 31;
    int t0 = blockIdx.x * 32 + warp * 4;

    float acc[4][NEXP];
#pragma unroll
    for (int tt = 0; tt < 4; tt++)
#pragma unroll
        for (int e = 0; e < NEXP; e++) acc[tt][e] = 0.f;

#pragma unroll
    for (int j = 0; j < DIM / 32; j++) {
        int k = lane + 32 * j;
        float xv[4];
#pragma unroll
        for (int tt = 0; tt < 4; tt++) {
            xv[tt] = x[(size_t)(t0 + tt) * DIM + k];
            __nv_bfloat16 h = __float2bfloat16_rn(xv[tt]);
            float hf = __bfloat162float(h);
            g_xh[(size_t)(t0 + tt) * DIM + k] = h;
            g_xl[(size_t)(t0 + tt) * DIM + k] = __float2bfloat16_rn(xv[tt] - hf);
        }
#pragma unroll
        for (int e = 0; e < NEXP; e++) {
            float w = s_w[e][k];
#pragma unroll
            for (int tt = 0; tt < 4; tt++)
                acc[tt][e] = fmaf(xv[tt], w, acc[tt][e]);
        }
    }
#pragma unroll
    for (int tt = 0; tt < 4; tt++)
#pragma unroll
        for (int e = 0; e < NEXP; e++)
#pragma unroll
            for (int off = 16; off > 0; off >>= 1)
                acc[tt][e] += __shfl_xor_sync(0xffffffffu, acc[tt][e], off);

#pragma unroll
    for (int tt = 0; tt < 4; tt++) {
        if (lane == tt) {
            float lmax = -1e30f; int am = 0;
#pragma unroll
            for (int e = 0; e < NEXP; e++) {
                float l = acc[tt][e] + s_b[e];
                acc[tt][e] = l;
                if (l > lmax) { lmax = l; am = e; }
            }
            float sum = 0.f;
#pragma unroll
            for (int e = 0; e < NEXP; e++) sum += expf(acc[tt][e] - lmax);
            g_routes[t0 + tt] = am;
            g_probs[t0 + tt]  = 1.f / sum;
        }
    }
}

// ---------------- 2) ordered rank within each expert queue ------------------
__global__ void rank_kernel() {
    int e = blockIdx.x;
    int tid = threadIdx.x, lane = tid & 31, wid = tid >> 5;
    __shared__ int s_ws[32];
    __shared__ int s_tot;
    int base = 0;
    const int4* r4 = (const int4*)g_routes;
#pragma unroll 1
    for (int c = 0; c < N_TOK / 4096; c++) {
        int4 r = r4[c * 1024 + tid];
        int f0 = (r.x == e), f1 = (r.y == e), f2 = (r.z == e), f3 = (r.w == e);
        int cnt = f0 + f1 + f2 + f3;
        int inc = cnt;
#pragma unroll
        for (int off = 1; off < 32; off <<= 1) {
            int o = __shfl_up_sync(0xffffffffu, inc, off);
            if (lane >= off) inc += o;
        }
        if (lane == 31) s_ws[wid] = inc;
        __syncthreads();
        if (wid == 0) {
            int v = s_ws[lane];
            int wi = v;
#pragma unroll
            for (int off = 1; off < 32; off <<= 1) {
                int o = __shfl_up_sync(0xffffffffu, wi, off);
                if (lane >= off) wi += o;
            }
            s_ws[lane] = wi - v;
            if (lane == 31) s_tot = wi;
        }
        __syncthreads();
        int ex = base + s_ws[wid] + (inc - cnt);
        int t = (c * 1024 + tid) * 4;
        if (f0) { g_pos[t]     = ex; if (ex < CAP) g_idx[e * CAP + ex] = t;     ex++; }
        if (f1) { g_pos[t + 1] = ex; if (ex < CAP) g_idx[e * CAP + ex] = t + 1; ex++; }
        if (f2) { g_pos[t + 2] = ex; if (ex < CAP) g_idx[e * CAP + ex] = t + 2; ex++; }
        if (f3) { g_pos[t + 3] = ex; if (ex < CAP) g_idx[e * CAP + ex] = t + 3; ex++; }
        base += s_tot;
        __syncthreads();
    }
    if (tid == 0) g_count[e] = base < CAP ? base : CAP;
}

// ---------------- 3) passthrough for dropped tokens (warp per token) --------
__global__ void passthrough_kernel(const float* __restrict__ x,
                                   float* __restrict__ out) {
    int warp = threadIdx.x >> 5, lane = threadIdx.x & 31;
    int t = blockIdx.x * 8 + warp;
    if (g_pos[t] >= CAP) {
        float p = g_probs[t];
        const float4* xr = (const float4*)(x + (size_t)t * DIM);
        float4* o = (float4*)(out + (size_t)t * DIM);
#pragma unroll
        for (int j = 0; j < 4; j++) {
            float4 v = xr[lane + 32 * j];
            v.x *= p; v.y *= p; v.z *= p; v.w *= p;
            o[lane + 32 * j] = v;
        }
    }
}

// ---------------- 4) mma.sync grouped gather-GEMM, fused combine ------------
// CTA tile 128x256x32, 512 threads / 16 warps (2m x 8n), warp tile 64x32.
// Split-bf16: D += Ah*Bh + Ah*Bl + Al*Bh, fp32 accum in registers.
#define BM 128
#define BN 256
#define BK 32
#define NSTG 3
#define OFF_AH 0
#define OFF_AL (8 * 1024)
#define OFF_BH (16 * 1024)
#define OFF_BL (32 * 1024)
#define STG_BYTES (48 * 1024)
#define SMEM_DYN  (NSTG * STG_BYTES + 1024)

__global__ void __launch_bounds__(512, 1)
moe_mma_kernel(const float* __restrict__ eb, float* __restrict__ out) {
    extern __shared__ char dynsmem[];
    __shared__ int   s_idx[BM];
    __shared__ float s_prob[BM];
    __shared__ float s_bias[BN];

    int e = blockIdx.z;
    int cnt = g_count[e];
    int m0 = blockIdx.x * BM;
    if (m0 >= cnt) return;
    int n0 = blockIdx.y * BN;
    int tid = threadIdx.x, wid = tid >> 5, lane = tid & 31;
    int wm = wid >> 3, wn = wid & 7;

    char* sbase = dynsmem + ((1024u - (smem_u32(dynsmem) & 1023u)) & 1023u);
    uint32_t u0 = smem_u32(sbase);

    if (tid < BM) {
        int m = m0 + tid;
        int t = g_idx[e * CAP + (m < cnt ? m : cnt - 1)];
        s_idx[tid] = t;
        s_prob[tid] = g_probs[t];
    }
    if (tid < BN) s_bias[tid] = eb[e * DIM + n0 + tid];
    __syncthreads();

    // cp.async slots: A = 1 per thread, B = 2 per thread (16B chunks)
    int a_row = tid >> 2, a_ch = tid & 3;
    size_t a_off = (size_t)s_idx[a_row] * DIM + a_ch * 8;
    const __nv_bfloat16* srcAh = g_xh + a_off;
    const __nv_bfloat16* srcAl = g_xl + a_off;
    uint32_t a_dst = swz((uint32_t)(a_row * 64 + a_ch * 16));

    const __nv_bfloat16 *srcBh[2], *srcBl[2];
    uint32_t b_dst[2];
#pragma unroll
    for (int i = 0; i < 2; i++) {
        int idx = tid + 512 * i;
        int row = idx >> 2, ch = idx & 3;
        size_t bo = (size_t)(e * DIM + n0 + row) * DIM + ch * 8;
        srcBh[i] = g_wh + bo;
        srcBl[i] = g_wl + bo;
        b_dst[i] = swz((uint32_t)(row * 64 + ch * 16));
    }

    const int KT = DIM / BK;   // 16
#pragma unroll
    for (int pre = 0; pre < 2; pre++) {
        uint32_t sb = u0 + pre * STG_BYTES;
        int kb = pre * BK;
        cp16(sb + OFF_AH + a_dst, srcAh + kb);
        cp16(sb + OFF_AL + a_dst, srcAl + kb);
#pragma unroll
        for (int i = 0; i < 2; i++) {
            cp16(sb + OFF_BH + b_dst[i], srcBh[i] + kb);
            cp16(sb + OFF_BL + b_dst[i], srcBl[i] + kb);
        }
        CP_COMMIT();
    }

    float acc[4][4][4];
#pragma unroll
    for (int mi = 0; mi < 4; mi++)
#pragma unroll
        for (int nj = 0; nj < 4; nj++)
#pragma unroll
            for (int k = 0; k < 4; k++) acc[mi][nj][k] = 0.f;

#pragma unroll 1
    for (int kt = 0; kt < KT; kt++) {
        CP_WAIT1();
        __syncthreads();
        if (kt + 2 < KT) {
            uint32_t sb = u0 + ((kt + 2) % NSTG) * STG_BYTES;
            int kb = (kt + 2) * BK;
            cp16(sb + OFF_AH + a_dst, srcAh + kb);
            cp16(sb + OFF_AL + a_dst, srcAl + kb);
#pragma unroll
            for (int i = 0; i < 2; i++) {
                cp16(sb + OFF_BH + b_dst[i], srcBh[i] + kb);
                cp16(sb + OFF_BL + b_dst[i], srcBl[i] + kb);
            }
            CP_COMMIT();
        } else {
            CP_COMMIT();   // keep group count in step
        }

        uint32_t sb = u0 + (kt % NSTG) * STG_BYTES;
#pragma unroll
        for (int ks = 0; ks < 2; ks++) {
            uint32_t ah[4][4], al[4][4], bh[4][2], bl[4][2];
#pragma unroll
            for (int mi = 0; mi < 4; mi++) {
                uint32_t off = (uint32_t)((wm * 64 + mi * 16 + (lane & 15)) * 64 +
                                          ks * 32 + (lane >> 4) * 16);
                uint32_t ad = sb + swz(off);
                ldsm4(ah[mi], ad + OFF_AH);
                ldsm4(al[mi], ad + OFF_AL);
            }
#pragma unroll
            for (int nj2 = 0; nj2 < 2; nj2++) {
                uint32_t off = (uint32_t)((wn * 32 + nj2 * 16 +
                                           ((lane >> 4) & 1) * 8 + (lane & 7)) * 64 +
                                          ks * 32 + ((lane >> 3) & 1) * 16);
                uint32_t bd = sb + swz(off);
                uint32_t r[4];
                ldsm4(r, bd + OFF_BH);
                bh[nj2 * 2][0] = r[0]; bh[nj2 * 2][1] = r[1];
                bh[nj2 * 2 + 1][0] = r[2]; bh[nj2 * 2 + 1][1] = r[3];
                ldsm4(r, bd + OFF_BL);
                bl[nj2 * 2][0] = r[0]; bl[nj2 * 2][1] = r[1];
                bl[nj2 * 2 + 1][0] = r[2]; bl[nj2 * 2 + 1][1] = r[3];
            }
#pragma unroll
            for (int mi = 0; mi < 4; mi++)
#pragma unroll
                for (int nj = 0; nj < 4; nj++) {
                    mma16816(acc[mi][nj], ah[mi], bh[nj]);
                    mma16816(acc[mi][nj], ah[mi], bl[nj]);
                    mma16816(acc[mi][nj], al[mi], bh[nj]);
                }
        }
    }

    // epilogue: +bias, *prob, scatter rows to out
#pragma unroll
    for (int mi = 0; mi < 4; mi++) {
        int r0 = wm * 64 + mi * 16 + (lane >> 2);
        int r1 = r0 + 8;
        bool ok0 = (m0 + r0) < cnt;
        bool ok1 = (m0 + r1) < cnt;
        float p0 = s_prob[r0], p1 = s_prob[r1];
        float* o0 = out + (size_t)s_idx[r0] * DIM + n0;
        float* o1 = out + (size_t)s_idx[r1] * DIM + n0;
#pragma unroll
        for (int nj = 0; nj < 4; nj++) {
            int col = wn * 32 + nj * 8 + 2 * (lane & 3);
            float b0 = s_bias[col], b1 = s_bias[col + 1];
            if (ok0) {
                float2 v = make_float2((acc[mi][nj][0] + b0) * p0,
                                       (acc[mi][nj][1] + b1) * p0);
                *(float2*)(o0 + col) = v;
            }
            if (ok1) {
                float2 v = make_float2((acc[mi][nj][2] + b0) * p1,
                                       (acc[mi][nj][3] + b1) * p1);
                *(float2*)(o1 + col) = v;
            }
        }
    }
}

// ---------------------------------------------------------------------------
extern "C" void kernel_launch(void* const* d_in, const int* in_sizes, int n_in,
                              void* d_out, int out_size) {
    const float* x   = (const float*)d_in[0];   // [N, D]
    const float* sw  = (const float*)d_in[1];   // [E, D]
    const float* sb  = (const float*)d_in[2];   // [E]
    const float* ew  = (const float*)d_in[3];   // [E, D, D]
    const float* ebv = (const float*)d_in[4];   // [E, D]
    float* out = (float*)d_out;

    cudaFuncSetAttribute(moe_mma_kernel,
                         cudaFuncAttributeMaxDynamicSharedMemorySize, SMEM_DYN);

    rw_kernel<<<RW_ROUTER_BLOCKS + RW_WCONV_BLOCKS, 256>>>(x, sw, sb, ew);
    rank_kernel<<<NEXP, 1024>>>();
    passthrough_kernel<<<N_TOK / 8, 256>>>(x, out);

    dim3 grid((CAP + BM - 1) / BM, DIM / BN, NEXP);
    moe_mma_kernel<<<grid, 512, SMEM_DYN>>>(ebv, out);
}

// round 5
// speedup vs baseline: 1.9779x; 1.0626x over previous
#include <cuda_runtime.h>
#include <cuda_bf16.h>
#include <cstdint>

// Fixed problem shape: B=8, S=4096, D=512, E=16
#define N_TOK 32768
#define DIM   512
#define NEXP  16
#define CAP   2457   // int(1.2 * 32768 / 16)

// ---------------- scratch (device globals; no allocation allowed) ----------
__device__ __align__(16) __nv_bfloat16 g_xh[N_TOK * DIM];
__device__ __align__(16) __nv_bfloat16 g_xl[N_TOK * DIM];
__device__ __align__(16) __nv_bfloat16 g_wh[NEXP * DIM * DIM];
__device__ __align__(16) __nv_bfloat16 g_wl[NEXP * DIM * DIM];
__device__ int   g_routes[N_TOK];
__device__ float g_probs[N_TOK];
__device__ int   g_pos[N_TOK];
__device__ int   g_idx[NEXP * CAP];
__device__ int   g_count[NEXP];

// ---------------- PTX helpers (baseline sm_80/sm_90 features only) ---------
__device__ __forceinline__ uint32_t smem_u32(const void* p) {
    uint32_t a;
    asm("{ .reg .u64 t; cvta.to.shared.u64 t, %1; cvt.u32.u64 %0, t; }"
        : "=r"(a) : "l"(p));
    return a;
}
__device__ __forceinline__ uint32_t swz(uint32_t b) {   // 64B-row swizzle
    return b ^ ((b >> 3) & 0x30);
}
__device__ __forceinline__ void cp16(uint32_t dst, const void* src) {
    asm volatile("cp.async.cg.shared.global [%0], [%1], 16;\n"
                 :: "r"(dst), "l"(src));
}
#define CP_COMMIT() asm volatile("cp.async.commit_group;\n" ::: "memory")
#define CP_WAIT2()  asm volatile("cp.async.wait_group 2;\n" ::: "memory")

__device__ __forceinline__ void ldsm4(uint32_t* r, uint32_t a) {
    asm volatile("ldmatrix.sync.aligned.m8n8.x4.shared.b16 {%0,%1,%2,%3}, [%4];\n"
                 : "=r"(r[0]), "=r"(r[1]), "=r"(r[2]), "=r"(r[3]) : "r"(a));
}
__device__ __forceinline__ void mma16816(float* d, const uint32_t* a,
                                         const uint32_t* b) {
    asm volatile(
        "mma.sync.aligned.m16n8k16.row.col.f32.bf16.bf16.f32 "
        "{%0,%1,%2,%3}, {%4,%5,%6,%7}, {%8,%9}, {%0,%1,%2,%3};\n"
        : "+f"(d[0]), "+f"(d[1]), "+f"(d[2]), "+f"(d[3])
        : "r"(a[0]), "r"(a[1]), "r"(a[2]), "r"(a[3]), "r"(b[0]), "r"(b[1]));
}

// ---------------- 1) fused router + x-split + W-split -----------------------
#define RW_ROUTER_BLOCKS (N_TOK / 32)                       // 1024
#define RW_WCONV_BLOCKS  (NEXP * DIM * DIM / 4 / 256)       // 4096

__global__ void __launch_bounds__(256)
rw_kernel(const float* __restrict__ x,
          const float* __restrict__ sw,
          const float* __restrict__ sb,
          const float* __restrict__ ew) {
    int tid = threadIdx.x;

    if (blockIdx.x >= RW_ROUTER_BLOCKS) {
        // ---- wconv part ----
        int idx = (blockIdx.x - RW_ROUTER_BLOCKS) * 256 + tid;   // float4 index
        float4 v = ((const float4*)ew)[idx];
        float hx = __bfloat162float(__float2bfloat16_rn(v.x));
        float hy = __bfloat162float(__float2bfloat16_rn(v.y));
        float hz = __bfloat162float(__float2bfloat16_rn(v.z));
        float hw = __bfloat162float(__float2bfloat16_rn(v.w));
        __nv_bfloat162 h0 = __floats2bfloat162_rn(hx, hy);
        __nv_bfloat162 h1 = __floats2bfloat162_rn(hz, hw);
        __nv_bfloat162 l0 = __floats2bfloat162_rn(v.x - hx, v.y - hy);
        __nv_bfloat162 l1 = __floats2bfloat162_rn(v.z - hz, v.w - hw);
        *(uint2*)(g_wh + (size_t)idx * 4) = make_uint2(*(uint32_t*)&h0, *(uint32_t*)&h1);
        *(uint2*)(g_wl + (size_t)idx * 4) = make_uint2(*(uint32_t*)&l0, *(uint32_t*)&l1);
        return;
    }

    // ---- router part ----
    __shared__ float s_w[NEXP][DIM];
    __shared__ float s_b[NEXP];
    for (int i = tid; i < NEXP * DIM / 4; i += 256)
        ((float4*)&s_w[0][0])[i] = ((const float4*)sw)[i];
    if (tid < NEXP) s_b[tid] = sb[tid];
    __syncthreads();

    int warp = tid >> 5, lane = tid & 31;
    int t0 = blockIdx.x * 32 + warp * 4;

    float acc[4][NEXP];
#pragma unroll
    for (int tt = 0; tt < 4; tt++)
#pragma unroll
        for (int e = 0; e < NEXP; e++) acc[tt][e] = 0.f;

#pragma unroll
    for (int j = 0; j < DIM / 32; j++) {
        int k = lane + 32 * j;
        float xv[4];
#pragma unroll
        for (int tt = 0; tt < 4; tt++) {
            xv[tt] = x[(size_t)(t0 + tt) * DIM + k];
            __nv_bfloat16 h = __float2bfloat16_rn(xv[tt]);
            float hf = __bfloat162float(h);
            g_xh[(size_t)(t0 + tt) * DIM + k] = h;
            g_xl[(size_t)(t0 + tt) * DIM + k] = __float2bfloat16_rn(xv[tt] - hf);
        }
#pragma unroll
        for (int e = 0; e < NEXP; e++) {
            float w = s_w[e][k];
#pragma unroll
            for (int tt = 0; tt < 4; tt++)
                acc[tt][e] = fmaf(xv[tt], w, acc[tt][e]);
        }
    }
#pragma unroll
    for (int tt = 0; tt < 4; tt++)
#pragma unroll
        for (int e = 0; e < NEXP; e++)
#pragma unroll
            for (int off = 16; off > 0; off >>= 1)
                acc[tt][e] += __shfl_xor_sync(0xffffffffu, acc[tt][e], off);

#pragma unroll
    for (int tt = 0; tt < 4; tt++) {
        if (lane == tt) {
            float lmax = -1e30f; int am = 0;
#pragma unroll
            for (int e = 0; e < NEXP; e++) {
                float l = acc[tt][e] + s_b[e];
                acc[tt][e] = l;
                if (l > lmax) { lmax = l; am = e; }
            }
            float sum = 0.f;
#pragma unroll
            for (int e = 0; e < NEXP; e++) sum += expf(acc[tt][e] - lmax);
            g_routes[t0 + tt] = am;
            g_probs[t0 + tt]  = 1.f / sum;
        }
    }
}

// ---------------- 2) ordered rank within each expert queue ------------------
__global__ void rank_kernel() {
    int e = blockIdx.x;
    int tid = threadIdx.x, lane = tid & 31, wid = tid >> 5;
    __shared__ int s_ws[32];
    __shared__ int s_tot;
    int base = 0;
    const int4* r4 = (const int4*)g_routes;
#pragma unroll 1
    for (int c = 0; c < N_TOK / 4096; c++) {
        int4 r = r4[c * 1024 + tid];
        int f0 = (r.x == e), f1 = (r.y == e), f2 = (r.z == e), f3 = (r.w == e);
        int cnt = f0 + f1 + f2 + f3;
        int inc = cnt;
#pragma unroll
        for (int off = 1; off < 32; off <<= 1) {
            int o = __shfl_up_sync(0xffffffffu, inc, off);
            if (lane >= off) inc += o;
        }
        if (lane == 31) s_ws[wid] = inc;
        __syncthreads();
        if (wid == 0) {
            int v = s_ws[lane];
            int wi = v;
#pragma unroll
            for (int off = 1; off < 32; off <<= 1) {
                int o = __shfl_up_sync(0xffffffffu, wi, off);
                if (lane >= off) wi += o;
            }
            s_ws[lane] = wi - v;
            if (lane == 31) s_tot = wi;
        }
        __syncthreads();
        int ex = base + s_ws[wid] + (inc - cnt);
        int t = (c * 1024 + tid) * 4;
        if (f0) { g_pos[t]     = ex; if (ex < CAP) g_idx[e * CAP + ex] = t;     ex++; }
        if (f1) { g_pos[t + 1] = ex; if (ex < CAP) g_idx[e * CAP + ex] = t + 1; ex++; }
        if (f2) { g_pos[t + 2] = ex; if (ex < CAP) g_idx[e * CAP + ex] = t + 2; ex++; }
        if (f3) { g_pos[t + 3] = ex; if (ex < CAP) g_idx[e * CAP + ex] = t + 3; ex++; }
        base += s_tot;
        __syncthreads();
    }
    if (tid == 0) g_count[e] = base < CAP ? base : CAP;
}

// ---------------- 3) passthrough for dropped tokens (warp per token) --------
__global__ void passthrough_kernel(const float* __restrict__ x,
                                   float* __restrict__ out) {
    int warp = threadIdx.x >> 5, lane = threadIdx.x & 31;
    int t = blockIdx.x * 8 + warp;
    if (g_pos[t] >= CAP) {
        float p = g_probs[t];
        const float4* xr = (const float4*)(x + (size_t)t * DIM);
        float4* o = (float4*)(out + (size_t)t * DIM);
#pragma unroll
        for (int j = 0; j < 4; j++) {
            float4 v = xr[lane + 32 * j];
            v.x *= p; v.y *= p; v.z *= p; v.w *= p;
            o[lane + 32 * j] = v;
        }
    }
}

// ---------------- 4) mma.sync grouped gather-GEMM, fused combine ------------
// CTA tile 128x256x32, 256 threads / 8 warps (2m x 4n), warp tile 64x64.
// Split-bf16: D += Ah*Bh + Ah*Bl + Al*Bh, fp32 accum in registers.
#define BM 128
#define BN 256
#define BK 32
#define NSTG 4
#define OFF_AH 0
#define OFF_AL (8 * 1024)
#define OFF_BH (16 * 1024)
#define OFF_BL (32 * 1024)
#define STG_BYTES (48 * 1024)
#define SMEM_DYN  (NSTG * STG_BYTES + 1024)

__global__ void __launch_bounds__(256, 1)
moe_mma_kernel(const float* __restrict__ eb, float* __restrict__ out) {
    extern __shared__ char dynsmem[];
    __shared__ int   s_idx[BM];
    __shared__ float s_prob[BM];
    __shared__ float s_bias[BN];

    int e = blockIdx.z;
    int cnt = g_count[e];
    int m0 = blockIdx.x * BM;
    if (m0 >= cnt) return;
    int n0 = blockIdx.y * BN;
    int tid = threadIdx.x, wid = tid >> 5, lane = tid & 31;
    int wm = wid >> 2, wn = wid & 3;

    char* sbase = dynsmem + ((1024u - (smem_u32(dynsmem) & 1023u)) & 1023u);
    uint32_t u0 = smem_u32(sbase);

    if (tid < BM) {
        int m = m0 + tid;
        int t = g_idx[e * CAP + (m < cnt ? m : cnt - 1)];
        s_idx[tid] = t;
        s_prob[tid] = g_probs[t];
    }
    s_bias[tid] = eb[e * DIM + n0 + tid];
    __syncthreads();

    // cp.async slots: A = 2 per thread, B = 4 per thread (16B chunks)
    const __nv_bfloat16 *srcAh[2], *srcAl[2];
    uint32_t a_dst[2];
#pragma unroll
    for (int i = 0; i < 2; i++) {
        int idx = tid + 256 * i;
        int row = idx >> 2, ch = idx & 3;
        size_t ao = (size_t)s_idx[row] * DIM + ch * 8;
        srcAh[i] = g_xh + ao;
        srcAl[i] = g_xl + ao;
        a_dst[i] = swz((uint32_t)(row * 64 + ch * 16));
    }
    const __nv_bfloat16 *srcBh[4], *srcBl[4];
    uint32_t b_dst[4];
#pragma unroll
    for (int i = 0; i < 4; i++) {
        int idx = tid + 256 * i;
        int row = idx >> 2, ch = idx & 3;
        size_t bo = (size_t)(e * DIM + n0 + row) * DIM + ch * 8;
        srcBh[i] = g_wh + bo;
        srcBl[i] = g_wl + bo;
        b_dst[i] = swz((uint32_t)(row * 64 + ch * 16));
    }

    const int KT = DIM / BK;   // 16
#pragma unroll
    for (int pre = 0; pre < 3; pre++) {
        uint32_t sb = u0 + pre * STG_BYTES;
        int kb = pre * BK;
#pragma unroll
        for (int i = 0; i < 2; i++) {
            cp16(sb + OFF_AH + a_dst[i], srcAh[i] + kb);
            cp16(sb + OFF_AL + a_dst[i], srcAl[i] + kb);
        }
#pragma unroll
        for (int i = 0; i < 4; i++) {
            cp16(sb + OFF_BH + b_dst[i], srcBh[i] + kb);
            cp16(sb + OFF_BL + b_dst[i], srcBl[i] + kb);
        }
        CP_COMMIT();
    }

    float acc[4][8][4];
#pragma unroll
    for (int mi = 0; mi < 4; mi++)
#pragma unroll
        for (int nj = 0; nj < 8; nj++)
#pragma unroll
            for (int k = 0; k < 4; k++) acc[mi][nj][k] = 0.f;

#pragma unroll 1
    for (int kt = 0; kt < KT; kt++) {
        CP_WAIT2();
        __syncthreads();
        if (kt + 3 < KT) {
            uint32_t sb = u0 + ((kt + 3) % NSTG) * STG_BYTES;
            int kb = (kt + 3) * BK;
#pragma unroll
            for (int i = 0; i < 2; i++) {
                cp16(sb + OFF_AH + a_dst[i], srcAh[i] + kb);
                cp16(sb + OFF_AL + a_dst[i], srcAl[i] + kb);
            }
#pragma unroll
            for (int i = 0; i < 4; i++) {
                cp16(sb + OFF_BH + b_dst[i], srcBh[i] + kb);
                cp16(sb + OFF_BL + b_dst[i], srcBl[i] + kb);
            }
        }
        CP_COMMIT();

        uint32_t sb = u0 + (kt % NSTG) * STG_BYTES;
#pragma unroll
        for (int ks = 0; ks < 2; ks++) {
            uint32_t ah[4][4], al[4][4], bh[8][2], bl[8][2];
#pragma unroll
            for (int mi = 0; mi < 4; mi++) {
                uint32_t off = (uint32_t)((wm * 64 + mi * 16 + (lane & 15)) * 64 +
                                          ks * 32 + (lane >> 4) * 16);
                uint32_t ad = sb + swz(off);
                ldsm4(ah[mi], ad + OFF_AH);
                ldsm4(al[mi], ad + OFF_AL);
            }
#pragma unroll
            for (int nj2 = 0; nj2 < 4; nj2++) {
                uint32_t off = (uint32_t)((wn * 64 + nj2 * 16 +
                                           ((lane >> 4) & 1) * 8 + (lane & 7)) * 64 +
                                          ks * 32 + ((lane >> 3) & 1) * 16);
                uint32_t bd = sb + swz(off);
                uint32_t r[4];
                ldsm4(r, bd + OFF_BH);
                bh[nj2 * 2][0] = r[0]; bh[nj2 * 2][1] = r[1];
                bh[nj2 * 2 + 1][0] = r[2]; bh[nj2 * 2 + 1][1] = r[3];
                ldsm4(r, bd + OFF_BL);
                bl[nj2 * 2][0] = r[0]; bl[nj2 * 2][1] = r[1];
                bl[nj2 * 2 + 1][0] = r[2]; bl[nj2 * 2 + 1][1] = r[3];
            }
#pragma unroll
            for (int mi = 0; mi < 4; mi++)
#pragma unroll
                for (int nj = 0; nj < 8; nj++) {
                    mma16816(acc[mi][nj], ah[mi], bh[nj]);
                    mma16816(acc[mi][nj], ah[mi], bl[nj]);
                    mma16816(acc[mi][nj], al[mi], bh[nj]);
                }
        }
    }

    // epilogue: +bias, *prob, scatter rows to out
#pragma unroll
    for (int mi = 0; mi < 4; mi++) {
        int r0 = wm * 64 + mi * 16 + (lane >> 2);
        int r1 = r0 + 8;
        bool ok0 = (m0 + r0) < cnt;
        bool ok1 = (m0 + r1) < cnt;
        float p0 = s_prob[r0], p1 = s_prob[r1];
        float* o0 = out + (size_t)s_idx[r0] * DIM + n0;
        float* o1 = out + (size_t)s_idx[r1] * DIM + n0;
#pragma unroll
        for (int nj = 0; nj < 8; nj++) {
            int col = wn * 64 + nj * 8 + 2 * (lane & 3);
            float b0 = s_bias[col], b1 = s_bias[col + 1];
            if (ok0) {
                float2 v = make_float2((acc[mi][nj][0] + b0) * p0,
                                       (acc[mi][nj][1] + b1) * p0);
                *(float2*)(o0 + col) = v;
            }
            if (ok1) {
                float2 v = make_float2((acc[mi][nj][2] + b0) * p1,
                                       (acc[mi][nj][3] + b1) * p1);
                *(float2*)(o1 + col) = v;
            }
        }
    }
}

// ---------------------------------------------------------------------------
extern "C" void kernel_launch(void* const* d_in, const int* in_sizes, int n_in,
                              void* d_out, int out_size) {
    const float* x   = (const float*)d_in[0];   // [N, D]
    const float* sw  = (const float*)d_in[1];   // [E, D]
    const float* sb  = (const float*)d_in[2];   // [E]
    const float* ew  = (const float*)d_in[3];   // [E, D, D]
    const float* ebv = (const float*)d_in[4];   // [E, D]
    float* out = (float*)d_out;

    cudaFuncSetAttribute(moe_mma_kernel,
                         cudaFuncAttributeMaxDynamicSharedMemorySize, SMEM_DYN);

    rw_kernel<<<RW_ROUTER_BLOCKS + RW_WCONV_BLOCKS, 256>>>(x, sw, sb, ew);
    rank_kernel<<<NEXP, 1024>>>();
    passthrough_kernel<<<N_TOK / 8, 256>>>(x, out);

    dim3 grid((CAP + BM - 1) / BM, DIM / BN, NEXP);
    moe_mma_kernel<<<grid, 256, SMEM_DYN>>>(ebv, out);
}

// round 6
// speedup vs baseline: 2.2608x; 1.1430x over previous
#include <cuda_runtime.h>
#include <cuda_bf16.h>
#include <cstdint>

// Fixed problem shape: B=8, S=4096, D=512, E=16
#define N_TOK 32768
#define DIM   512
#define NEXP  16
#define CAP   2457   // int(1.2 * 32768 / 16)
#define NBLK  1024   // router blocks (32 tokens each)

// ---------------- scratch (device globals; no allocation allowed) ----------
__device__ __align__(16) __nv_bfloat16 g_xh[N_TOK * DIM];
__device__ __align__(16) __nv_bfloat16 g_xl[N_TOK * DIM];
__device__ __align__(16) __nv_bfloat16 g_wh[NEXP * DIM * DIM];
__device__ __align__(16) __nv_bfloat16 g_wl[NEXP * DIM * DIM];
__device__ int   g_routes[N_TOK];
__device__ float g_probs[N_TOK];
__device__ int   g_blkcnt[NEXP * NBLK];
__device__ int   g_blkoff[NEXP * NBLK];
__device__ int   g_idx[NEXP * CAP];
__device__ int   g_count[NEXP];

// ---------------- PTX helpers ----------------------------------------------
__device__ __forceinline__ uint32_t smem_u32(const void* p) {
    uint32_t a;
    asm("{ .reg .u64 t; cvta.to.shared.u64 t, %1; cvt.u32.u64 %0, t; }"
        : "=r"(a) : "l"(p));
    return a;
}
__device__ __forceinline__ uint32_t swz(uint32_t b) {   // 64B-row swizzle
    return b ^ ((b >> 3) & 0x30);
}
__device__ __forceinline__ void cp16(uint32_t dst, const void* src) {
    asm volatile("cp.async.cg.shared.global [%0], [%1], 16;\n"
                 :: "r"(dst), "l"(src));
}
#define CP_COMMIT() asm volatile("cp.async.commit_group;\n" ::: "memory")
#define CP_WAIT1()  asm volatile("cp.async.wait_group 1;\n" ::: "memory")

__device__ __forceinline__ void ldsm4(uint32_t* r, uint32_t a) {
    asm volatile("ldmatrix.sync.aligned.m8n8.x4.shared.b16 {%0,%1,%2,%3}, [%4];\n"
                 : "=r"(r[0]), "=r"(r[1]), "=r"(r[2]), "=r"(r[3]) : "r"(a));
}
__device__ __forceinline__ void mma16816(float* d, const uint32_t* a,
                                         const uint32_t* b) {
    asm volatile(
        "mma.sync.aligned.m16n8k16.row.col.f32.bf16.bf16.f32 "
        "{%0,%1,%2,%3}, {%4,%5,%6,%7}, {%8,%9}, {%0,%1,%2,%3};\n"
        : "+f"(d[0]), "+f"(d[1]), "+f"(d[2]), "+f"(d[3])
        : "r"(a[0]), "r"(a[1]), "r"(a[2]), "r"(a[3]), "r"(b[0]), "r"(b[1]));
}

// ---------------- 1) fused router + x-split + W-split + block counts --------
#define RW_ROUTER_BLOCKS NBLK                               // 1024
#define RW_WCONV_BLOCKS  (NEXP * DIM * DIM / 4 / 256)       // 4096

__global__ void __launch_bounds__(256)
rw_kernel(const float* __restrict__ x,
          const float* __restrict__ sw,
          const float* __restrict__ sb,
          const float* __restrict__ ew) {
    int tid = threadIdx.x;

    if (blockIdx.x >= RW_ROUTER_BLOCKS) {
        // ---- wconv part ----
        int idx = (blockIdx.x - RW_ROUTER_BLOCKS) * 256 + tid;   // float4 index
        float4 v = ((const float4*)ew)[idx];
        float hx = __bfloat162float(__float2bfloat16_rn(v.x));
        float hy = __bfloat162float(__float2bfloat16_rn(v.y));
        float hz = __bfloat162float(__float2bfloat16_rn(v.z));
        float hw = __bfloat162float(__float2bfloat16_rn(v.w));
        __nv_bfloat162 h0 = __floats2bfloat162_rn(hx, hy);
        __nv_bfloat162 h1 = __floats2bfloat162_rn(hz, hw);
        __nv_bfloat162 l0 = __floats2bfloat162_rn(v.x - hx, v.y - hy);
        __nv_bfloat162 l1 = __floats2bfloat162_rn(v.z - hz, v.w - hw);
        *(uint2*)(g_wh + (size_t)idx * 4) = make_uint2(*(uint32_t*)&h0, *(uint32_t*)&h1);
        *(uint2*)(g_wl + (size_t)idx * 4) = make_uint2(*(uint32_t*)&l0, *(uint32_t*)&l1);
        return;
    }

    // ---- router part ----
    __shared__ float s_w[NEXP][DIM];
    __shared__ float s_b[NEXP];
    __shared__ int   s_routes[32];
    for (int i = tid; i < NEXP * DIM / 4; i += 256)
        ((float4*)&s_w[0][0])[i] = ((const float4*)sw)[i];
    if (tid < NEXP) s_b[tid] = sb[tid];
    __syncthreads();

    int warp = tid >> 5, lane = tid & 31;
    int t0 = blockIdx.x * 32 + warp * 4;

    float acc[4][NEXP];
#pragma unroll
    for (int tt = 0; tt < 4; tt++)
#pragma unroll
        for (int e = 0; e < NEXP; e++) acc[tt][e] = 0.f;

#pragma unroll
    for (int j = 0; j < DIM / 32; j++) {
        int k = lane + 32 * j;
        float xv[4];
#pragma unroll
        for (int tt = 0; tt < 4; tt++) {
            xv[tt] = x[(size_t)(t0 + tt) * DIM + k];
            __nv_bfloat16 h = __float2bfloat16_rn(xv[tt]);
            float hf = __bfloat162float(h);
            g_xh[(size_t)(t0 + tt) * DIM + k] = h;
            g_xl[(size_t)(t0 + tt) * DIM + k] = __float2bfloat16_rn(xv[tt] - hf);
        }
#pragma unroll
        for (int e = 0; e < NEXP; e++) {
            float w = s_w[e][k];
#pragma unroll
            for (int tt = 0; tt < 4; tt++)
                acc[tt][e] = fmaf(xv[tt], w, acc[tt][e]);
        }
    }
#pragma unroll
    for (int tt = 0; tt < 4; tt++)
#pragma unroll
        for (int e = 0; e < NEXP; e++)
#pragma unroll
            for (int off = 16; off > 0; off >>= 1)
                acc[tt][e] += __shfl_xor_sync(0xffffffffu, acc[tt][e], off);

#pragma unroll
    for (int tt = 0; tt < 4; tt++) {
        if (lane == tt) {
            float lmax = -1e30f; int am = 0;
#pragma unroll
            for (int e = 0; e < NEXP; e++) {
                float l = acc[tt][e] + s_b[e];
                acc[tt][e] = l;
                if (l > lmax) { lmax = l; am = e; }
            }
            float sum = 0.f;
#pragma unroll
            for (int e = 0; e < NEXP; e++) sum += expf(acc[tt][e] - lmax);
            g_routes[t0 + tt] = am;
            g_probs[t0 + tt]  = 1.f / sum;
            s_routes[warp * 4 + tt] = am;
        }
    }
    __syncthreads();
    // per-(block, expert) counts
    if (tid < NEXP) {
        int c = 0;
#pragma unroll
        for (int i = 0; i < 32; i++) c += (s_routes[i] == tid);
        g_blkcnt[tid * NBLK + blockIdx.x] = c;
    }
}

// ---------------- 2) per-expert exclusive scan over blocks ------------------
__global__ void __launch_bounds__(1024)
scan_kernel() {
    int e = blockIdx.x;
    int tid = threadIdx.x, lane = tid & 31, wid = tid >> 5;
    __shared__ int s_ws[32];
    int v = g_blkcnt[e * NBLK + tid];
    int inc = v;
#pragma unroll
    for (int off = 1; off < 32; off <<= 1) {
        int o = __shfl_up_sync(0xffffffffu, inc, off);
        if (lane >= off) inc += o;
    }
    if (lane == 31) s_ws[wid] = inc;
    __syncthreads();
    if (wid == 0) {
        int w = s_ws[lane];
        int wi = w;
#pragma unroll
        for (int off = 1; off < 32; off <<= 1) {
            int o = __shfl_up_sync(0xffffffffu, wi, off);
            if (lane >= off) wi += o;
        }
        s_ws[lane] = wi - w;
    }
    __syncthreads();
    int excl = s_ws[wid] + inc - v;
    g_blkoff[e * NBLK + tid] = excl;
    if (tid == 1023) {
        int tot = excl + v;
        g_count[e] = tot < CAP ? tot : CAP;
    }
}

// ---------------- 3) finalize: ranks + g_idx + dropped-token passthrough ----
__global__ void __launch_bounds__(256)
finalize_kernel(const float* __restrict__ x, float* __restrict__ out) {
    __shared__ unsigned s_drop;
    int blk = blockIdx.x;
    int tid = threadIdx.x;
    if (tid < 32) {
        int t = blk * 32 + tid;
        int r = g_routes[t];
        unsigned mask = __match_any_sync(0xffffffffu, r);
        int rank = __popc(mask & ((1u << tid) - 1u));
        int pos = g_blkoff[r * NBLK + blk] + rank;
        bool keep = pos < CAP;
        if (keep) g_idx[r * CAP + pos] = t;
        unsigned dm = __ballot_sync(0xffffffffu, !keep);
        if (tid == 0) s_drop = dm;
    }
    __syncthreads();
    unsigned dm = s_drop;
    while (dm) {
        int d = __ffs(dm) - 1;
        dm &= dm - 1;
        int t = blk * 32 + d;
        float p = g_probs[t];
        if (tid < 128) {
            float4 v = ((const float4*)(x + (size_t)t * DIM))[tid];
            v.x *= p; v.y *= p; v.z *= p; v.w *= p;
            ((float4*)(out + (size_t)t * DIM))[tid] = v;
        }
    }
}

// ---------------- 4) mma.sync grouped gather-GEMM, fused combine ------------
// CTA tile 128x128x32, 256 threads / 8 warps (2m x 4n), warp tile 64x32.
// 2 CTAs per SM (regs capped at 128, smem 96KB + static).
#define BM 128
#define BN 128
#define BK 32
#define NSTG 3
#define OFF_AH 0
#define OFF_AL (8 * 1024)
#define OFF_BH (16 * 1024)
#define OFF_BL (24 * 1024)
#define STG_BYTES (32 * 1024)
#define SMEM_DYN  (NSTG * STG_BYTES + 1024)

__global__ void __launch_bounds__(256, 2)
moe_mma_kernel(const float* __restrict__ eb, float* __restrict__ out) {
    extern __shared__ char dynsmem[];
    __shared__ int   s_idx[BM];
    __shared__ float s_prob[BM];
    __shared__ float s_bias[BN];

    int e = blockIdx.z;
    int cnt = g_count[e];
    int m0 = blockIdx.x * BM;
    if (m0 >= cnt) return;
    int n0 = blockIdx.y * BN;
    int tid = threadIdx.x, wid = tid >> 5, lane = tid & 31;
    int wm = wid >> 2, wn = wid & 3;

    char* sbase = dynsmem + ((1024u - (smem_u32(dynsmem) & 1023u)) & 1023u);
    uint32_t u0 = smem_u32(sbase);

    if (tid < BM) {
        int m = m0 + tid;
        int t = g_idx[e * CAP + (m < cnt ? m : cnt - 1)];
        s_idx[tid] = t;
        s_prob[tid] = g_probs[t];
    }
    if (tid < BN) s_bias[tid] = eb[e * DIM + n0 + tid];
    __syncthreads();

    // cp.async slots: 2 per thread per term (A and B)
    const __nv_bfloat16 *srcAh[2], *srcAl[2], *srcBh[2], *srcBl[2];
    uint32_t a_dst[2], b_dst[2];
#pragma unroll
    for (int i = 0; i < 2; i++) {
        int idx = tid + 256 * i;
        int row = idx >> 2, ch = idx & 3;
        size_t ao = (size_t)s_idx[row] * DIM + ch * 8;
        srcAh[i] = g_xh + ao;
        srcAl[i] = g_xl + ao;
        size_t bo = (size_t)(e * DIM + n0 + row) * DIM + ch * 8;
        srcBh[i] = g_wh + bo;
        srcBl[i] = g_wl + bo;
        a_dst[i] = swz((uint32_t)(row * 64 + ch * 16));
        b_dst[i] = a_dst[i];
    }

    const int KT = DIM / BK;   // 16
#pragma unroll
    for (int pre = 0; pre < 2; pre++) {
        uint32_t sb = u0 + pre * STG_BYTES;
        int kb = pre * BK;
#pragma unroll
        for (int i = 0; i < 2; i++) {
            cp16(sb + OFF_AH + a_dst[i], srcAh[i] + kb);
            cp16(sb + OFF_AL + a_dst[i], srcAl[i] + kb);
            cp16(sb + OFF_BH + b_dst[i], srcBh[i] + kb);
            cp16(sb + OFF_BL + b_dst[i], srcBl[i] + kb);
        }
        CP_COMMIT();
    }

    float acc[4][4][4];
#pragma unroll
    for (int mi = 0; mi < 4; mi++)
#pragma unroll
        for (int nj = 0; nj < 4; nj++)
#pragma unroll
            for (int k = 0; k < 4; k++) acc[mi][nj][k] = 0.f;

#pragma unroll 1
    for (int kt = 0; kt < KT; kt++) {
        CP_WAIT1();
        __syncthreads();
        if (kt + 2 < KT) {
            uint32_t sb = u0 + ((kt + 2) % NSTG) * STG_BYTES;
            int kb = (kt + 2) * BK;
#pragma unroll
            for (int i = 0; i < 2; i++) {
                cp16(sb + OFF_AH + a_dst[i], srcAh[i] + kb);
                cp16(sb + OFF_AL + a_dst[i], srcAl[i] + kb);
                cp16(sb + OFF_BH + b_dst[i], srcBh[i] + kb);
                cp16(sb + OFF_BL + b_dst[i], srcBl[i] + kb);
            }
        }
        CP_COMMIT();

        uint32_t sb = u0 + (kt % NSTG) * STG_BYTES;
#pragma unroll
        for (int ks = 0; ks < 2; ks++) {
            uint32_t ah[4][4], al[4][4], bh[4][2], bl[4][2];
#pragma unroll
            for (int mi = 0; mi < 4; mi++) {
                uint32_t off = (uint32_t)((wm * 64 + mi * 16 + (lane & 15)) * 64 +
                                          ks * 32 + (lane >> 4) * 16);
                uint32_t ad = sb + swz(off);
                ldsm4(ah[mi], ad + OFF_AH);
                ldsm4(al[mi], ad + OFF_AL);
            }
#pragma unroll
            for (int nj2 = 0; nj2 < 2; nj2++) {
                uint32_t off = (uint32_t)((wn * 32 + nj2 * 16 +
                                           ((lane >> 4) & 1) * 8 + (lane & 7)) * 64 +
                                          ks * 32 + ((lane >> 3) & 1) * 16);
                uint32_t bd = sb + swz(off);
                uint32_t r[4];
                ldsm4(r, bd + OFF_BH);
                bh[nj2 * 2][0] = r[0]; bh[nj2 * 2][1] = r[1];
                bh[nj2 * 2 + 1][0] = r[2]; bh[nj2 * 2 + 1][1] = r[3];
                ldsm4(r, bd + OFF_BL);
                bl[nj2 * 2][0] = r[0]; bl[nj2 * 2][1] = r[1];
                bl[nj2 * 2 + 1][0] = r[2]; bl[nj2 * 2 + 1][1] = r[3];
            }
#pragma unroll
            for (int mi = 0; mi < 4; mi++)
#pragma unroll
                for (int nj = 0; nj < 4; nj++) {
                    mma16816(acc[mi][nj], ah[mi], bh[nj]);
                    mma16816(acc[mi][nj], ah[mi], bl[nj]);
                    mma16816(acc[mi][nj], al[mi], bh[nj]);
                }
        }
    }

    // epilogue: +bias, *prob, scatter rows to out
#pragma unroll
    for (int mi = 0; mi < 4; mi++) {
        int r0 = wm * 64 + mi * 16 + (lane >> 2);
        int r1 = r0 + 8;
        bool ok0 = (m0 + r0) < cnt;
        bool ok1 = (m0 + r1) < cnt;
        float p0 = s_prob[r0], p1 = s_prob[r1];
        float* o0 = out + (size_t)s_idx[r0] * DIM + n0;
        float* o1 = out + (size_t)s_idx[r1] * DIM + n0;
#pragma unroll
        for (int nj = 0; nj < 4; nj++) {
            int col = wn * 32 + nj * 8 + 2 * (lane & 3);
            float b0 = s_bias[col], b1 = s_bias[col + 1];
            if (ok0) {
                float2 v = make_float2((acc[mi][nj][0] + b0) * p0,
                                       (acc[mi][nj][1] + b1) * p0);
                *(float2*)(o0 + col) = v;
            }
            if (ok1) {
                float2 v = make_float2((acc[mi][nj][2] + b0) * p1,
                                       (acc[mi][nj][3] + b1) * p1);
                *(float2*)(o1 + col) = v;
            }
        }
    }
}

// ---------------------------------------------------------------------------
extern "C" void kernel_launch(void* const* d_in, const int* in_sizes, int n_in,
                              void* d_out, int out_size) {
    const float* x   = (const float*)d_in[0];   // [N, D]
    const float* sw  = (const float*)d_in[1];   // [E, D]
    const float* sb  = (const float*)d_in[2];   // [E]
    const float* ew  = (const float*)d_in[3];   // [E, D, D]
    const float* ebv = (const float*)d_in[4];   // [E, D]
    float* out = (float*)d_out;

    cudaFuncSetAttribute(moe_mma_kernel,
                         cudaFuncAttributeMaxDynamicSharedMemorySize, SMEM_DYN);

    rw_kernel<<<RW_ROUTER_BLOCKS + RW_WCONV_BLOCKS, 256>>>(x, sw, sb, ew);
    scan_kernel<<<NEXP, 1024>>>();
    finalize_kernel<<<NBLK, 256>>>(x, out);

    dim3 grid((CAP + BM - 1) / BM, DIM / BN, NEXP);
    moe_mma_kernel<<<grid, 256, SMEM_DYN>>>(ebv, out);
}